// round 12
// baseline (speedup 1.0000x reference)
#include <cuda_runtime.h>
#include <cuda_fp16.h>

#define N_NODES 100000
#define N_EDGES 6400000
#define F 32
#define STRIDE 160              // padded bucket slots per node (>>12 sigma of deg)
#define FULL 0xffffffffu

// ---------------- scratch (no allocations allowed) ----------------
__device__ int    g_cnt[N_NODES];           // in-degree / scatter cursor (zeroed at tail of each run)
__device__ float  g_dis[N_NODES];           // deg^{-1/2} (deg incl. self-loop)
__device__ int    g_csrc[N_NODES * STRIDE]; // padded CSR: src per slot (64MB)
__device__ uint2  g_x4h[N_NODES];           // x as half4 {x0,x1 | x2,0}, dis-scaled
__device__ uint4  g_h1h[N_NODES * 4];       // dis*relu(h1) as fp16, 32 halfs/row
__device__ __half g_t3h[N_NODES];           // dis*(relu(.)@W3) as fp16 (200KB ~ L1)

// ---- cache-policy load helpers ----
__device__ __forceinline__ int ld_cs(const int* p) {
    int v; asm("ld.global.cs.b32 %0, [%1];" : "=r"(v) : "l"(p)); return v;
}
__device__ __forceinline__ int4 ld_cs4(const int4* p) {
    int4 v; asm("ld.global.cs.v4.b32 {%0,%1,%2,%3}, [%4];"
                : "=r"(v.x), "=r"(v.y), "=r"(v.z), "=r"(v.w) : "l"(p));
    return v;
}
__device__ __forceinline__ uint2 ld_el8(const uint2* p) {
    uint2 v; asm("ld.global.nc.L1::evict_last.v2.b32 {%0,%1}, [%2];"
                 : "=r"(v.x), "=r"(v.y) : "l"(p));
    return v;
}
__device__ __forceinline__ unsigned short ld_el2(const __half* p) {
    unsigned short v; asm("ld.global.nc.L1::evict_last.b16 %0, [%1];"
                          : "=h"(v) : "l"(p));
    return v;
}

// ---------------- init: pack x to half4 (cnt already zero) ----------------
__global__ void k_init(const float* __restrict__ x) {
    int i = blockIdx.x * blockDim.x + threadIdx.x;
    if (i < N_NODES) {
        __half2 lo = __floats2half2_rn(x[3 * i],     x[3 * i + 1]);
        __half2 hi = __floats2half2_rn(x[3 * i + 2], 0.0f);
        g_x4h[i] = make_uint2(*(unsigned*)&lo, *(unsigned*)&hi);
    }
}

// ---------------- combined count+scatter: 16 edges/thread for deep MLP --------
__global__ void k_scatter(const int4* __restrict__ src4, const int4* __restrict__ dst4) {
    int t = blockIdx.x * blockDim.x + threadIdx.x;
    if (t >= N_EDGES / 16) return;
#pragma unroll
    for (int q = 0; q < 2; q++) {
        int4 d0 = ld_cs4(&dst4[4 * t + 2 * q]),     d1 = ld_cs4(&dst4[4 * t + 2 * q + 1]);
        int4 s0 = ld_cs4(&src4[4 * t + 2 * q]),     s1 = ld_cs4(&src4[4 * t + 2 * q + 1]);
        int a0 = atomicAdd(&g_cnt[d0.x], 1);
        int a1 = atomicAdd(&g_cnt[d0.y], 1);
        int a2 = atomicAdd(&g_cnt[d0.z], 1);
        int a3 = atomicAdd(&g_cnt[d0.w], 1);
        int a4 = atomicAdd(&g_cnt[d1.x], 1);
        int a5 = atomicAdd(&g_cnt[d1.y], 1);
        int a6 = atomicAdd(&g_cnt[d1.z], 1);
        int a7 = atomicAdd(&g_cnt[d1.w], 1);
        if (a0 < STRIDE) g_csrc[d0.x * STRIDE + a0] = s0.x;
        if (a1 < STRIDE) g_csrc[d0.y * STRIDE + a1] = s0.y;
        if (a2 < STRIDE) g_csrc[d0.z * STRIDE + a2] = s0.z;
        if (a3 < STRIDE) g_csrc[d0.w * STRIDE + a3] = s0.w;
        if (a4 < STRIDE) g_csrc[d1.x * STRIDE + a4] = s1.x;
        if (a5 < STRIDE) g_csrc[d1.y * STRIDE + a5] = s1.y;
        if (a6 < STRIDE) g_csrc[d1.z * STRIDE + a6] = s1.z;
        if (a7 < STRIDE) g_csrc[d1.w * STRIDE + a7] = s1.w;
    }
}

// ---------------- post: dis = rsqrt(deg+1), pre-scale packed x ----------------
__global__ void k_post() {
    int i = blockIdx.x * blockDim.x + threadIdx.x;
    if (i < N_NODES) {
        float di = rsqrtf((float)g_cnt[i] + 1.0f);   // +1 self-loop
        g_dis[i] = di;
        uint2 q = g_x4h[i];
        float2 lo = __half22float2(*(__half2*)&q.x);
        float2 hi = __half22float2(*(__half2*)&q.y);
        __half2 l2 = __floats2half2_rn(lo.x * di, lo.y * di);
        __half2 h2 = __floats2half2_rn(hi.x * di, 0.0f);
        g_x4h[i] = make_uint2(*(unsigned*)&l2, *(unsigned*)&h2);
    }
}

// ---------------- fused layer 1: 4 nodes/warp, 16 loads in flight ------------
__global__ void k_agg4_t1(const float* __restrict__ W1, const float* __restrict__ b1) {
    __shared__ float Ws[3 * F];
    for (int j = threadIdx.x; j < 3 * F; j += blockDim.x) Ws[j] = W1[j];
    __syncthreads();

    int w = (blockIdx.x * blockDim.x + threadIdx.x) >> 5;
    int lane = threadIdx.x & 31;
    int i0 = 4 * w;                        // N_NODES % 4 == 0 -> all valid
    if (i0 >= N_NODES) return;

    int n[4], o[4];
#pragma unroll
    for (int p = 0; p < 4; p++) {
        o[p] = (i0 + p) * STRIDE;
        n[p] = min(g_cnt[i0 + p], STRIDE);
    }
    int nmax = max(max(n[0], n[1]), max(n[2], n[3]));

    float acc[12];
#pragma unroll
    for (int k = 0; k < 12; k++) acc[k] = 0.f;

    for (int base = 0; base < nmax; base += 64) {
        int e0 = base + lane, e1 = base + 32 + lane;
        int idx[8];
#pragma unroll
        for (int p = 0; p < 4; p++) {
            idx[2 * p]     = (e0 < n[p]) ? ld_cs(&g_csrc[o[p] + e0]) : -1;
            idx[2 * p + 1] = (e1 < n[p]) ? ld_cs(&g_csrc[o[p] + e1]) : -1;
        }
#pragma unroll
        for (int q = 0; q < 8; q++) {
            if (idx[q] >= 0) {
                uint2 v = ld_el8(&g_x4h[idx[q]]);
                float2 lo = __half22float2(*(__half2*)&v.x);
                float2 hi = __half22float2(*(__half2*)&v.y);
                int p = q >> 1;
                acc[3 * p]     += lo.x;
                acc[3 * p + 1] += lo.y;
                acc[3 * p + 2] += hi.x;
            }
        }
    }
#pragma unroll
    for (int d = 16; d > 0; d >>= 1)
#pragma unroll
        for (int k = 0; k < 12; k++) acc[k] += __shfl_xor_sync(FULL, acc[k], d);

#pragma unroll
    for (int p = 0; p < 4; p++) {
        int i = i0 + p;
        float di = g_dis[i];
        uint2 sq = g_x4h[i];               // self-loop (already dis-scaled)
        float2 slo = __half22float2(*(__half2*)&sq.x);
        float2 shi = __half22float2(*(__half2*)&sq.y);
        float ax = (acc[3 * p]     + slo.x) * di;
        float ay = (acc[3 * p + 1] + slo.y) * di;
        float az = (acc[3 * p + 2] + shi.x) * di;

        float t = b1[lane];
        t = fmaf(ax, Ws[0 * F + lane], t);
        t = fmaf(ay, Ws[1 * F + lane], t);
        t = fmaf(az, Ws[2 * F + lane], t);
        t = fmaxf(t, 0.0f) * di;           // pre-scale by dis for next agg

        float thi = __shfl_down_sync(FULL, t, 1);
        if ((lane & 1) == 0) {
            __half2 h2 = __floats2half2_rn(t, thi);
            ((unsigned*)g_h1h)[i * 16 + (lane >> 1)] = *(unsigned*)&h2;
        }
    }
}

// ---------------- fused layer 2+3: 2 nodes/warp, pipelined idx loads ---------
__global__ void k_agg32_t2t3(const float* __restrict__ W2, const float* __restrict__ b2,
                             const float* __restrict__ W3) {
    __shared__ float Ws[F * F];
    __shared__ float W3s[F];
    __shared__ float stage[8 * 2 * F];     // 8 warps x 2 nodes per 256-thr block
    for (int j = threadIdx.x; j < F * F; j += blockDim.x) Ws[j] = W2[j];
    if (threadIdx.x < F) W3s[threadIdx.x] = W3[threadIdx.x];
    __syncthreads();

    int w = (blockIdx.x * blockDim.x + threadIdx.x) >> 5;
    int lane = threadIdx.x & 31;
    int wib  = (threadIdx.x >> 5);
    int iA = 2 * w, iB = iA + 1;
    if (iA >= N_NODES) return;
    int oA = iA * STRIDE, oB = iB * STRIDE;
    int nA = min(g_cnt[iA], STRIDE), nB = min(g_cnt[iB], STRIDE);
    int nmax = max(nA, nB);

    int c   = lane & 3;                    // 16B chunk of the 64B fp16 row
    int sub = lane >> 2;                   // edge slot within group of 8

    float a[16];
#pragma unroll
    for (int k = 0; k < 16; k++) a[k] = 0.f;

    // prefetch batch 0 indices
    int sA = (lane < nA) ? ld_cs(&g_csrc[oA + lane]) : 0;
    int sB = (lane < nB) ? ld_cs(&g_csrc[oB + lane]) : 0;

    for (int base = 0; base < nmax; base += 32) {
        // prefetch next batch while consuming this one
        int ne = base + 32 + lane;
        int sA2 = (ne < nA) ? ld_cs(&g_csrc[oA + ne]) : 0;
        int sB2 = (ne < nB) ? ld_cs(&g_csrc[oB + ne]) : 0;

        int remA = nA - base, remB = nB - base;

        if (remA >= 32) {
#pragma unroll
            for (int j0 = 0; j0 < 32; j0 += 8) {
                int sj = __shfl_sync(FULL, sA, j0 + sub);
                uint4 q = __ldg(&g_h1h[sj * 4 + c]);
                __half2* hp = (__half2*)&q;
#pragma unroll
                for (int k = 0; k < 4; k++) {
                    float2 f = __half22float2(hp[k]);
                    a[2 * k]     += f.x;
                    a[2 * k + 1] += f.y;
                }
            }
        } else if (remA > 0) {
#pragma unroll
            for (int j0 = 0; j0 < 32; j0 += 8) {
                if (j0 >= remA) break;
                int j = j0 + sub;
                int sj = __shfl_sync(FULL, sA, j);
                if (j < remA) {
                    uint4 q = __ldg(&g_h1h[sj * 4 + c]);
                    __half2* hp = (__half2*)&q;
#pragma unroll
                    for (int k = 0; k < 4; k++) {
                        float2 f = __half22float2(hp[k]);
                        a[2 * k]     += f.x;
                        a[2 * k + 1] += f.y;
                    }
                }
            }
        }

        if (remB >= 32) {
#pragma unroll
            for (int j0 = 0; j0 < 32; j0 += 8) {
                int sj = __shfl_sync(FULL, sB, j0 + sub);
                uint4 q = __ldg(&g_h1h[sj * 4 + c]);
                __half2* hp = (__half2*)&q;
#pragma unroll
                for (int k = 0; k < 4; k++) {
                    float2 f = __half22float2(hp[k]);
                    a[8 + 2 * k]     += f.x;
                    a[8 + 2 * k + 1] += f.y;
                }
            }
        } else if (remB > 0) {
#pragma unroll
            for (int j0 = 0; j0 < 32; j0 += 8) {
                if (j0 >= remB) break;
                int j = j0 + sub;
                int sj = __shfl_sync(FULL, sB, j);
                if (j < remB) {
                    uint4 q = __ldg(&g_h1h[sj * 4 + c]);
                    __half2* hp = (__half2*)&q;
#pragma unroll
                    for (int k = 0; k < 4; k++) {
                        float2 f = __half22float2(hp[k]);
                        a[8 + 2 * k]     += f.x;
                        a[8 + 2 * k + 1] += f.y;
                    }
                }
            }
        }
        sA = sA2; sB = sB2;
    }
#pragma unroll
    for (int d = 4; d <= 16; d <<= 1)
#pragma unroll
        for (int k = 0; k < 16; k++) a[k] += __shfl_xor_sync(FULL, a[k], d);

    if (sub == 0) {                        // lanes 0..3: 8 features per node
#pragma unroll
        for (int p = 0; p < 2; p++) {
            int i = (p == 0) ? iA : iB;
            float di = g_dis[i];
            uint4 q = g_h1h[i * 4 + c];    // self-loop (pre-scaled row)
            __half2* hp = (__half2*)&q;
            float* ap = &a[8 * p];
            float* st = &stage[(wib * 2 + p) * F + c * 8];
#pragma unroll
            for (int k = 0; k < 4; k++) {
                float2 f = __half22float2(hp[k]);
                st[2 * k]     = (ap[2 * k]     + f.x) * di;
                st[2 * k + 1] = (ap[2 * k + 1] + f.y) * di;
            }
        }
    }
    __syncwarp();

#pragma unroll
    for (int p = 0; p < 2; p++) {
        int i = (p == 0) ? iA : iB;
        float av = stage[(wib * 2 + p) * F + lane];
        float t = b2[lane];
#pragma unroll
        for (int k = 0; k < F; k++) {
            float ak = __shfl_sync(FULL, av, k);
            t = fmaf(ak, Ws[k * F + lane], t);
        }
        float v = fmaxf(t, 0.0f) * W3s[lane];
#pragma unroll
        for (int d = 16; d > 0; d >>= 1) v += __shfl_xor_sync(FULL, v, d);
        if (lane == 0) g_t3h[i] = __float2half(v * g_dis[i]);
    }
}

// ---------------- layer 3: 4 nodes/warp, fp16 t3 gather; zero cnt at tail ----
__global__ void k_agg1f(const float* __restrict__ b3, float* __restrict__ out) {
    int w = (blockIdx.x * blockDim.x + threadIdx.x) >> 5;
    int lane = threadIdx.x & 31;
    int i0 = 4 * w;
    if (i0 >= N_NODES) return;

    int n[4], o[4];
#pragma unroll
    for (int p = 0; p < 4; p++) {
        o[p] = (i0 + p) * STRIDE;
        n[p] = min(g_cnt[i0 + p], STRIDE);
    }
    int nmax = max(max(n[0], n[1]), max(n[2], n[3]));

    float acc[4];
#pragma unroll
    for (int p = 0; p < 4; p++) acc[p] = 0.f;

    for (int base = 0; base < nmax; base += 64) {
        int e0 = base + lane, e1 = base + 32 + lane;
        int idx[8];
#pragma unroll
        for (int p = 0; p < 4; p++) {
            idx[2 * p]     = (e0 < n[p]) ? ld_cs(&g_csrc[o[p] + e0]) : -1;
            idx[2 * p + 1] = (e1 < n[p]) ? ld_cs(&g_csrc[o[p] + e1]) : -1;
        }
#pragma unroll
        for (int q = 0; q < 8; q++) {
            if (idx[q] >= 0) {
                unsigned short h = ld_el2(&g_t3h[idx[q]]);
                acc[q >> 1] += __half2float(*(__half*)&h);
            }
        }
    }
#pragma unroll
    for (int d = 16; d > 0; d >>= 1)
#pragma unroll
        for (int p = 0; p < 4; p++) acc[p] += __shfl_xor_sync(FULL, acc[p], d);

    if (lane < 4) {
        int i = i0 + lane;
        float a = (lane == 0) ? acc[0] : (lane == 1) ? acc[1]
                : (lane == 2) ? acc[2] : acc[3];
        // acc[p] identical on all lanes post-reduction; pick per-lane
        out[i] = fmaf(a + __half2float(g_t3h[i]), g_dis[i], b3[0]);
        g_cnt[i] = 0;                      // ready for next replay
    }
}

// ---------------- launcher ----------------
extern "C" void kernel_launch(void* const* d_in, const int* in_sizes, int n_in,
                              void* d_out, int out_size) {
    const float* x  = (const float*)d_in[0];
    const int*   ei = (const int*)  d_in[1];
    const float* W1 = (const float*)d_in[2];
    const float* b1 = (const float*)d_in[3];
    const float* W2 = (const float*)d_in[4];
    const float* b2 = (const float*)d_in[5];
    const float* W3 = (const float*)d_in[6];
    const float* b3 = (const float*)d_in[7];

    const int4* src4 = (const int4*)ei;               // edge_index[0]
    const int4* dst4 = (const int4*)(ei + N_EDGES);   // edge_index[1]
    float* out = (float*)d_out;

    const int TB = 256;
    int gN   = (N_NODES + TB - 1) / TB;               // thread-per-node
    int gE16 = (N_EDGES / 16 + TB - 1) / TB;          // thread per 16 edges
    int gNW2 = ((N_NODES / 2) * 32 + TB - 1) / TB;    // warp per 2 nodes
    int gNW4 = ((N_NODES / 4) * 32 + TB - 1) / TB;    // warp per 4 nodes

    k_init<<<gN, TB>>>(x);
    k_scatter<<<gE16, TB>>>(src4, dst4);              // count + place, one pass
    k_post<<<gN, TB>>>();

    k_agg4_t1<<<gNW4, TB>>>(W1, b1);                  // layer 1 fused
    k_agg32_t2t3<<<gNW2, TB>>>(W2, b2, W3);           // layers 2+3 fused
    k_agg1f<<<gNW4, TB>>>(b3, out);                   // final agg -> out, cnt reset
}

// round 13
// speedup vs baseline: 1.0132x; 1.0132x over previous
#include <cuda_runtime.h>
#include <cuda_fp16.h>

#define N_NODES 100000
#define N_EDGES 6400000
#define F 32
#define STRIDE 160              // padded bucket slots per node (>>12 sigma of deg)
#define FULL 0xffffffffu

// ---------------- scratch (no allocations allowed) ----------------
__device__ int    g_cnt[N_NODES];           // in-degree / cursor (zeroed at tail of each run)
__device__ float  g_dis[N_NODES];           // deg^{-1/2} (deg incl. self-loop)
__device__ int    g_csrc[N_NODES * STRIDE]; // padded CSR: src per slot (64MB)
__device__ uint2  g_x4h[N_NODES];           // x as half4 {x0,x1 | x2,0}, dis-scaled
__device__ uint4  g_h1h[N_NODES * 4];       // dis*relu(h1) as fp16, 32 halfs/row
__device__ __half g_t3h[N_NODES];           // dis*(relu(.)@W3) as fp16 (200KB ~ L1)

// ---- cache-policy load helpers ----
__device__ __forceinline__ int ld_cs(const int* p) {
    int v; asm("ld.global.cs.b32 %0, [%1];" : "=r"(v) : "l"(p)); return v;
}
__device__ __forceinline__ int4 ld_cs4(const int4* p) {
    int4 v; asm("ld.global.cs.v4.b32 {%0,%1,%2,%3}, [%4];"
                : "=r"(v.x), "=r"(v.y), "=r"(v.z), "=r"(v.w) : "l"(p));
    return v;
}
__device__ __forceinline__ uint2 ld_el8(const uint2* p) {
    uint2 v; asm("ld.global.nc.L1::evict_last.v2.b32 {%0,%1}, [%2];"
                 : "=r"(v.x), "=r"(v.y) : "l"(p));
    return v;
}
__device__ __forceinline__ unsigned short ld_el2(const __half* p) {
    unsigned short v; asm("ld.global.nc.L1::evict_last.b16 %0, [%1];"
                          : "=h"(v) : "l"(p));
    return v;
}

// ---------------- combined count+scatter: 16 edges/thread ----------
__global__ void k_scatter(const int4* __restrict__ src4, const int4* __restrict__ dst4) {
    int t = blockIdx.x * blockDim.x + threadIdx.x;
    if (t >= N_EDGES / 16) return;
#pragma unroll
    for (int q = 0; q < 2; q++) {
        int4 d0 = ld_cs4(&dst4[4 * t + 2 * q]), d1 = ld_cs4(&dst4[4 * t + 2 * q + 1]);
        int4 s0 = ld_cs4(&src4[4 * t + 2 * q]), s1 = ld_cs4(&src4[4 * t + 2 * q + 1]);
        int a0 = atomicAdd(&g_cnt[d0.x], 1);
        int a1 = atomicAdd(&g_cnt[d0.y], 1);
        int a2 = atomicAdd(&g_cnt[d0.z], 1);
        int a3 = atomicAdd(&g_cnt[d0.w], 1);
        int a4 = atomicAdd(&g_cnt[d1.x], 1);
        int a5 = atomicAdd(&g_cnt[d1.y], 1);
        int a6 = atomicAdd(&g_cnt[d1.z], 1);
        int a7 = atomicAdd(&g_cnt[d1.w], 1);
        if (a0 < STRIDE) g_csrc[d0.x * STRIDE + a0] = s0.x;
        if (a1 < STRIDE) g_csrc[d0.y * STRIDE + a1] = s0.y;
        if (a2 < STRIDE) g_csrc[d0.z * STRIDE + a2] = s0.z;
        if (a3 < STRIDE) g_csrc[d0.w * STRIDE + a3] = s0.w;
        if (a4 < STRIDE) g_csrc[d1.x * STRIDE + a4] = s1.x;
        if (a5 < STRIDE) g_csrc[d1.y * STRIDE + a5] = s1.y;
        if (a6 < STRIDE) g_csrc[d1.z * STRIDE + a6] = s1.z;
        if (a7 < STRIDE) g_csrc[d1.w * STRIDE + a7] = s1.w;
    }
}

// ---------------- post: dis = rsqrt(deg+1); pack + pre-scale x ----------------
__global__ void k_post(const float* __restrict__ x) {
    int i = blockIdx.x * blockDim.x + threadIdx.x;
    if (i < N_NODES) {
        float di = rsqrtf((float)g_cnt[i] + 1.0f);   // +1 self-loop
        g_dis[i] = di;
        __half2 lo = __floats2half2_rn(x[3 * i] * di,     x[3 * i + 1] * di);
        __half2 hi = __floats2half2_rn(x[3 * i + 2] * di, 0.0f);
        g_x4h[i] = make_uint2(*(unsigned*)&lo, *(unsigned*)&hi);
    }
}

// ---------------- fused layer 1: 2 nodes/warp, 4 gathers in flight ----------
__global__ void k_agg4_t1(const float* __restrict__ W1, const float* __restrict__ b1) {
    __shared__ float Ws[3 * F];
    for (int j = threadIdx.x; j < 3 * F; j += blockDim.x) Ws[j] = W1[j];
    __syncthreads();

    int w = (blockIdx.x * blockDim.x + threadIdx.x) >> 5;
    int lane = threadIdx.x & 31;
    int iA = 2 * w, iB = iA + 1;           // N_NODES even -> both valid
    if (iA >= N_NODES) return;
    int oA = iA * STRIDE, oB = iB * STRIDE;
    int nA = min(g_cnt[iA], STRIDE), nB = min(g_cnt[iB], STRIDE);
    int nmax = max(nA, nB);

    float axA = 0.f, ayA = 0.f, azA = 0.f;
    float axB = 0.f, ayB = 0.f, azB = 0.f;
    for (int base = 0; base < nmax; base += 64) {
        int e0 = base + lane, e1 = base + 32 + lane;
        int sA0 = (e0 < nA) ? ld_cs(&g_csrc[oA + e0]) : -1;
        int sA1 = (e1 < nA) ? ld_cs(&g_csrc[oA + e1]) : -1;
        int sB0 = (e0 < nB) ? ld_cs(&g_csrc[oB + e0]) : -1;
        int sB1 = (e1 < nB) ? ld_cs(&g_csrc[oB + e1]) : -1;
        if (sA0 >= 0) {
            uint2 q = ld_el8(&g_x4h[sA0]);
            float2 lo = __half22float2(*(__half2*)&q.x);
            float2 hi = __half22float2(*(__half2*)&q.y);
            axA += lo.x; ayA += lo.y; azA += hi.x;
        }
        if (sA1 >= 0) {
            uint2 q = ld_el8(&g_x4h[sA1]);
            float2 lo = __half22float2(*(__half2*)&q.x);
            float2 hi = __half22float2(*(__half2*)&q.y);
            axA += lo.x; ayA += lo.y; azA += hi.x;
        }
        if (sB0 >= 0) {
            uint2 q = ld_el8(&g_x4h[sB0]);
            float2 lo = __half22float2(*(__half2*)&q.x);
            float2 hi = __half22float2(*(__half2*)&q.y);
            axB += lo.x; ayB += lo.y; azB += hi.x;
        }
        if (sB1 >= 0) {
            uint2 q = ld_el8(&g_x4h[sB1]);
            float2 lo = __half22float2(*(__half2*)&q.x);
            float2 hi = __half22float2(*(__half2*)&q.y);
            axB += lo.x; ayB += lo.y; azB += hi.x;
        }
    }
#pragma unroll
    for (int d = 16; d > 0; d >>= 1) {
        axA += __shfl_xor_sync(FULL, axA, d);
        ayA += __shfl_xor_sync(FULL, ayA, d);
        azA += __shfl_xor_sync(FULL, azA, d);
        axB += __shfl_xor_sync(FULL, axB, d);
        ayB += __shfl_xor_sync(FULL, ayB, d);
        azB += __shfl_xor_sync(FULL, azB, d);
    }

#pragma unroll
    for (int p = 0; p < 2; p++) {
        int i = (p == 0) ? iA : iB;
        float ax = (p == 0) ? axA : axB;
        float ay = (p == 0) ? ayA : ayB;
        float az = (p == 0) ? azA : azB;
        float di = g_dis[i];
        uint2 sq = g_x4h[i];               // self-loop (already dis-scaled)
        float2 slo = __half22float2(*(__half2*)&sq.x);
        float2 shi = __half22float2(*(__half2*)&sq.y);
        ax = (ax + slo.x) * di;
        ay = (ay + slo.y) * di;
        az = (az + shi.x) * di;

        float t = b1[lane];
        t = fmaf(ax, Ws[0 * F + lane], t);
        t = fmaf(ay, Ws[1 * F + lane], t);
        t = fmaf(az, Ws[2 * F + lane], t);
        t = fmaxf(t, 0.0f) * di;           // pre-scale by dis for next agg

        float thi = __shfl_down_sync(FULL, t, 1);
        if ((lane & 1) == 0) {
            __half2 h2 = __floats2half2_rn(t, thi);
            ((unsigned*)g_h1h)[i * 16 + (lane >> 1)] = *(unsigned*)&h2;
        }
    }
}

// ---------------- fused layer 2+3: 2 nodes/warp, pipelined idx loads ---------
__global__ void k_agg32_t2t3(const float* __restrict__ W2, const float* __restrict__ b2,
                             const float* __restrict__ W3) {
    __shared__ float Ws[F * F];
    __shared__ float W3s[F];
    __shared__ float stage[8 * 2 * F];     // 8 warps x 2 nodes per 256-thr block
    for (int j = threadIdx.x; j < F * F; j += blockDim.x) Ws[j] = W2[j];
    if (threadIdx.x < F) W3s[threadIdx.x] = W3[threadIdx.x];
    __syncthreads();

    int w = (blockIdx.x * blockDim.x + threadIdx.x) >> 5;
    int lane = threadIdx.x & 31;
    int wib  = (threadIdx.x >> 5);
    int iA = 2 * w, iB = iA + 1;
    if (iA >= N_NODES) return;
    int oA = iA * STRIDE, oB = iB * STRIDE;
    int nA = min(g_cnt[iA], STRIDE), nB = min(g_cnt[iB], STRIDE);
    int nmax = max(nA, nB);

    int c   = lane & 3;                    // 16B chunk of the 64B fp16 row
    int sub = lane >> 2;                   // edge slot within group of 8

    float a[16];
#pragma unroll
    for (int k = 0; k < 16; k++) a[k] = 0.f;

    // prefetch batch 0 indices
    int sA = (lane < nA) ? ld_cs(&g_csrc[oA + lane]) : 0;
    int sB = (lane < nB) ? ld_cs(&g_csrc[oB + lane]) : 0;

    for (int base = 0; base < nmax; base += 32) {
        // prefetch next batch while consuming this one
        int ne = base + 32 + lane;
        int sA2 = (ne < nA) ? ld_cs(&g_csrc[oA + ne]) : 0;
        int sB2 = (ne < nB) ? ld_cs(&g_csrc[oB + ne]) : 0;

        int remA = nA - base, remB = nB - base;

        if (remA >= 32) {
#pragma unroll
            for (int j0 = 0; j0 < 32; j0 += 8) {
                int sj = __shfl_sync(FULL, sA, j0 + sub);
                uint4 q = __ldg(&g_h1h[sj * 4 + c]);
                __half2* hp = (__half2*)&q;
#pragma unroll
                for (int k = 0; k < 4; k++) {
                    float2 f = __half22float2(hp[k]);
                    a[2 * k]     += f.x;
                    a[2 * k + 1] += f.y;
                }
            }
        } else if (remA > 0) {
#pragma unroll
            for (int j0 = 0; j0 < 32; j0 += 8) {
                if (j0 >= remA) break;
                int j = j0 + sub;
                int sj = __shfl_sync(FULL, sA, j);
                if (j < remA) {
                    uint4 q = __ldg(&g_h1h[sj * 4 + c]);
                    __half2* hp = (__half2*)&q;
#pragma unroll
                    for (int k = 0; k < 4; k++) {
                        float2 f = __half22float2(hp[k]);
                        a[2 * k]     += f.x;
                        a[2 * k + 1] += f.y;
                    }
                }
            }
        }

        if (remB >= 32) {
#pragma unroll
            for (int j0 = 0; j0 < 32; j0 += 8) {
                int sj = __shfl_sync(FULL, sB, j0 + sub);
                uint4 q = __ldg(&g_h1h[sj * 4 + c]);
                __half2* hp = (__half2*)&q;
#pragma unroll
                for (int k = 0; k < 4; k++) {
                    float2 f = __half22float2(hp[k]);
                    a[8 + 2 * k]     += f.x;
                    a[8 + 2 * k + 1] += f.y;
                }
            }
        } else if (remB > 0) {
#pragma unroll
            for (int j0 = 0; j0 < 32; j0 += 8) {
                if (j0 >= remB) break;
                int j = j0 + sub;
                int sj = __shfl_sync(FULL, sB, j);
                if (j < remB) {
                    uint4 q = __ldg(&g_h1h[sj * 4 + c]);
                    __half2* hp = (__half2*)&q;
#pragma unroll
                    for (int k = 0; k < 4; k++) {
                        float2 f = __half22float2(hp[k]);
                        a[8 + 2 * k]     += f.x;
                        a[8 + 2 * k + 1] += f.y;
                    }
                }
            }
        }
        sA = sA2; sB = sB2;
    }
#pragma unroll
    for (int d = 4; d <= 16; d <<= 1)
#pragma unroll
        for (int k = 0; k < 16; k++) a[k] += __shfl_xor_sync(FULL, a[k], d);

    if (sub == 0) {                        // lanes 0..3: 8 features per node
#pragma unroll
        for (int p = 0; p < 2; p++) {
            int i = (p == 0) ? iA : iB;
            float di = g_dis[i];
            uint4 q = g_h1h[i * 4 + c];    // self-loop (pre-scaled row)
            __half2* hp = (__half2*)&q;
            float* ap = &a[8 * p];
            float* st = &stage[(wib * 2 + p) * F + c * 8];
#pragma unroll
            for (int k = 0; k < 4; k++) {
                float2 f = __half22float2(hp[k]);
                st[2 * k]     = (ap[2 * k]     + f.x) * di;
                st[2 * k + 1] = (ap[2 * k + 1] + f.y) * di;
            }
        }
    }
    __syncwarp();

#pragma unroll
    for (int p = 0; p < 2; p++) {
        int i = (p == 0) ? iA : iB;
        float av = stage[(wib * 2 + p) * F + lane];
        float t = b2[lane];
#pragma unroll
        for (int k = 0; k < F; k++) {
            float ak = __shfl_sync(FULL, av, k);
            t = fmaf(ak, Ws[k * F + lane], t);
        }
        float v = fmaxf(t, 0.0f) * W3s[lane];
#pragma unroll
        for (int d = 16; d > 0; d >>= 1) v += __shfl_xor_sync(FULL, v, d);
        if (lane == 0) g_t3h[i] = __float2half(v * g_dis[i]);
    }
}

// ---------------- layer 3: 4 nodes/warp, fp16 t3 gather; zero cnt at tail ----
__global__ void k_agg1f(const float* __restrict__ b3, float* __restrict__ out) {
    int w = (blockIdx.x * blockDim.x + threadIdx.x) >> 5;
    int lane = threadIdx.x & 31;
    int i0 = 4 * w;
    if (i0 >= N_NODES) return;

    int n[4], o[4];
#pragma unroll
    for (int p = 0; p < 4; p++) {
        o[p] = (i0 + p) * STRIDE;
        n[p] = min(g_cnt[i0 + p], STRIDE);
    }
    int nmax = max(max(n[0], n[1]), max(n[2], n[3]));

    float acc[4];
#pragma unroll
    for (int p = 0; p < 4; p++) acc[p] = 0.f;

    for (int base = 0; base < nmax; base += 64) {
        int e0 = base + lane, e1 = base + 32 + lane;
        int idx[8];
#pragma unroll
        for (int p = 0; p < 4; p++) {
            idx[2 * p]     = (e0 < n[p]) ? ld_cs(&g_csrc[o[p] + e0]) : -1;
            idx[2 * p + 1] = (e1 < n[p]) ? ld_cs(&g_csrc[o[p] + e1]) : -1;
        }
#pragma unroll
        for (int q = 0; q < 8; q++) {
            if (idx[q] >= 0) {
                unsigned short h = ld_el2(&g_t3h[idx[q]]);
                acc[q >> 1] += __half2float(*(__half*)&h);
            }
        }
    }
#pragma unroll
    for (int d = 16; d > 0; d >>= 1)
#pragma unroll
        for (int p = 0; p < 4; p++) acc[p] += __shfl_xor_sync(FULL, acc[p], d);

    if (lane < 4) {
        int i = i0 + lane;
        float a = (lane == 0) ? acc[0] : (lane == 1) ? acc[1]
                : (lane == 2) ? acc[2] : acc[3];
        out[i] = fmaf(a + __half2float(g_t3h[i]), g_dis[i], b3[0]);
        g_cnt[i] = 0;                      // ready for next replay
    }
}

// ---------------- launcher ----------------
extern "C" void kernel_launch(void* const* d_in, const int* in_sizes, int n_in,
                              void* d_out, int out_size) {
    const float* x  = (const float*)d_in[0];
    const int*   ei = (const int*)  d_in[1];
    const float* W1 = (const float*)d_in[2];
    const float* b1 = (const float*)d_in[3];
    const float* W2 = (const float*)d_in[4];
    const float* b2 = (const float*)d_in[5];
    const float* W3 = (const float*)d_in[6];
    const float* b3 = (const float*)d_in[7];

    const int4* src4 = (const int4*)ei;               // edge_index[0]
    const int4* dst4 = (const int4*)(ei + N_EDGES);   // edge_index[1]
    float* out = (float*)d_out;

    const int TB = 256;
    int gN   = (N_NODES + TB - 1) / TB;               // thread-per-node
    int gE16 = (N_EDGES / 16 + TB - 1) / TB;          // thread per 16 edges
    int gNW2 = ((N_NODES / 2) * 32 + TB - 1) / TB;    // warp per 2 nodes
    int gNW4 = ((N_NODES / 4) * 32 + TB - 1) / TB;    // warp per 4 nodes

    k_scatter<<<gE16, TB>>>(src4, dst4);              // count + place, one pass
    k_post<<<gN, TB>>>(x);                            // dis + pack/scale x

    k_agg4_t1<<<gNW2, TB>>>(W1, b1);                  // layer 1 fused
    k_agg32_t2t3<<<gNW2, TB>>>(W2, b2, W3);           // layers 2+3 fused
    k_agg1f<<<gNW4, TB>>>(b3, out);                   // final agg -> out, cnt reset
}